// round 8
// baseline (speedup 1.0000x reference)
#include <cuda_runtime.h>
#include <math.h>

#define NB    512
#define NK    64
#define NC    2048
#define BDIM  128
#define SPLIT 2                       // CTAs per batch row
#define CHPB  (NC / SPLIT)            // 1024 channels per CTA
#define CPT   (CHPB / BDIM)           // 8 channels per thread
#define NPAIR (CPT / 2)               // 4 packed pairs per thread

typedef unsigned long long ull;

__device__ __forceinline__ ull pack2(float lo, float hi) {
    ull r;
    asm("mov.b64 %0, {%1, %2};" : "=l"(r) : "f"(lo), "f"(hi));
    return r;
}
__device__ __forceinline__ void unpack2(ull v, float& lo, float& hi) {
    asm("mov.b64 {%0, %1}, %2;" : "=f"(lo), "=f"(hi) : "l"(v));
}
__device__ __forceinline__ ull fma2(ull a, ull b, ull c) {
    ull r;
    asm("fma.rn.f32x2 %0, %1, %2, %3;" : "=l"(r) : "l"(a), "l"(b), "l"(c));
    return r;
}
__device__ __forceinline__ ull add2(ull a, ull b) {
    ull r;
    asm("add.rn.f32x2 %0, %1, %2;" : "=l"(r) : "l"(a), "l"(b));
    return r;
}
__device__ __forceinline__ float ex2a(float x) {
    float r;
    asm("ex2.approx.ftz.f32 %0, %1;" : "=f"(r) : "f"(x));
    return r;
}
__device__ __forceinline__ float lg2a(float x) {
    float r;
    asm("lg2.approx.ftz.f32 %0, %1;" : "=f"(r) : "f"(x));
    return r;
}

__global__ __launch_bounds__(BDIM)
void mixture_kernel(const float* __restrict__ mo,
                    const float* __restrict__ X,
                    float* __restrict__ out) {
    // 64B-aligned coefficient record per k: [A B | C D | E F | pad pad]
    __shared__ __align__(16) ulonglong2 sCo[NK][4];

    const int b    = blockIdx.x / SPLIT;
    const int part = blockIdx.x % SPLIT;
    const int tid  = threadIdx.x;

    // --- per-(b,k) coefficient precompute (first 64 threads) ---
    if (tid < NK) {
        const float* p = mo + ((size_t)b * NK + tid) * 6;
        float w  = p[0];
        float m1 = p[1];
        float m2 = p[2];
        float s1 = p[3];
        float s2 = p[4];
        float r  = p[5];

        float omr2 = 1.0f - r * r;
        float inv  = 1.0f / omr2;
        float is1  = 1.0f / s1;
        float is2  = 1.0f / s2;

        const float L2E = 1.4426950408889634f;   // log2(e)
        float a  = -0.5f * inv * is1 * is1 * L2E;
        float bb =  r    * inv * is1 * is2 * L2E;
        float cc = -0.5f * inv * is2 * is2 * L2E;

        float d = -(2.0f * a  * m1 + bb * m2);
        float e = -(2.0f * cc * m2 + bb * m1);
        // fold weight/normalizer into exponent: W * 2^q == 2^(q + log2 W)
        float W = w * is1 * is2 * rsqrtf(omr2) * 0.15915494309189535f;
        float f = a * m1 * m1 + bb * m1 * m2 + cc * m2 * m2 + lg2a(W);

        sCo[tid][0] = make_ulonglong2(pack2(a,  a),  pack2(bb, bb));
        sCo[tid][1] = make_ulonglong2(pack2(cc, cc), pack2(d,  d));
        sCo[tid][2] = make_ulonglong2(pack2(e,  e),  pack2(f,  f));
    }
    __syncthreads();

    // --- per-thread packed channel state (4 pairs = 8 channels) ---
    const int base = part * CHPB;
    const float2* Xb = reinterpret_cast<const float2*>(X) + (size_t)b * NC + base;

    ull xx[NPAIR], yy[NPAIR], acc[NPAIR];
    #pragma unroll
    for (int p = 0; p < NPAIR; p++) {
        float2 v0 = Xb[tid + (2 * p)     * BDIM];
        float2 v1 = Xb[tid + (2 * p + 1) * BDIM];
        xx[p]  = pack2(v0.x, v1.x);
        yy[p]  = pack2(v0.y, v1.y);
        acc[p] = 0ull;
    }

    // packed constants for FMA-pipe exp2 polynomial (hoisted into registers)
    const ull ONE2    = pack2(1.0f, 1.0f);
    const ull NEGONE2 = pack2(-1.0f, -1.0f);
    const ull MAGIC2  = pack2(12582912.0f, 12582912.0f);   // 1.5 * 2^23
    const ull P4 = pack2(0.009618129107628477f, 0.009618129107628477f);
    const ull P3 = pack2(0.05550410866482158f,  0.05550410866482158f);
    const ull P2 = pack2(0.2402265069591007f,   0.2402265069591007f);
    const ull P1 = pack2(0.6931471805599453f,   0.6931471805599453f);
    const int  EXPC = 127 - 0x4B400000;                     // (bits - magic_bits + bias)

    // even k: all 8 exps on MUFU; odd k: pairs 0-2 MUFU, pair 3 FMA-pipe poly
    #pragma unroll 2
    for (int k2 = 0; k2 < NK; k2 += 2) {
        // ---------------- body A (k2): all MUFU ----------------
        {
            const ulonglong2 c01 = sCo[k2][0];
            const ulonglong2 c23 = sCo[k2][1];
            const ulonglong2 c45 = sCo[k2][2];
            const ull AA = c01.x, BB = c01.y;
            const ull CC = c23.x, DD = c23.y;
            const ull EE = c45.x, FF = c45.y;

            #pragma unroll
            for (int p = 0; p < NPAIR; p++) {
                ull u = fma2(AA, xx[p], fma2(BB, yy[p], DD));
                ull v = fma2(CC, yy[p], EE);
                ull q = fma2(u, xx[p], fma2(v, yy[p], FF));
                float q0, q1;
                unpack2(q, q0, q1);
                ull ee = pack2(ex2a(q0), ex2a(q1));
                acc[p] = add2(ee, acc[p]);
            }
        }
        // ---------------- body B (k2+1): pair 3 via poly ----------------
        {
            const ulonglong2 c01 = sCo[k2 + 1][0];
            const ulonglong2 c23 = sCo[k2 + 1][1];
            const ulonglong2 c45 = sCo[k2 + 1][2];
            const ull AA = c01.x, BB = c01.y;
            const ull CC = c23.x, DD = c23.y;
            const ull EE = c45.x, FF = c45.y;

            #pragma unroll
            for (int p = 0; p < NPAIR - 1; p++) {
                ull u = fma2(AA, xx[p], fma2(BB, yy[p], DD));
                ull v = fma2(CC, yy[p], EE);
                ull q = fma2(u, xx[p], fma2(v, yy[p], FF));
                float q0, q1;
                unpack2(q, q0, q1);
                ull ee = pack2(ex2a(q0), ex2a(q1));
                acc[p] = add2(ee, acc[p]);
            }
            // pair 3: packed FMA-pipe exp2
            {
                const int p = NPAIR - 1;
                ull u = fma2(AA, xx[p], fma2(BB, yy[p], DD));
                ull v = fma2(CC, yy[p], EE);
                ull q = fma2(u, xx[p], fma2(v, yy[p], FF));

                // clamp (scalar FMNMX, alu pipe) for underflow safety
                float q0, q1;
                unpack2(q, q0, q1);
                q0 = fmaxf(q0, -126.0f);
                q1 = fmaxf(q1, -126.0f);
                ull qc = pack2(q0, q1);

                // range reduction: n = rne(q), f = q - n in [-0.5, 0.5]
                ull t   = add2(qc, MAGIC2);           // low bits of halves hold n
                ull mnf = fma2(t, NEGONE2, MAGIC2);   // magic - t == -n (as float)
                ull f   = add2(qc, mnf);              // q - n

                // poly: 2^f ~= 1 + f(P1 + f(P2 + f(P3 + f*P4)))
                ull pl = fma2(P4, f, P3);
                pl = fma2(pl, f, P2);
                pl = fma2(pl, f, P1);
                pl = fma2(pl, f, ONE2);

                // scale = 2^n per half via exponent-bit reconstruction (LEA, alu)
                float t0, t1;
                unpack2(t, t0, t1);
                int i0 = __float_as_int(t0);
                int i1 = __float_as_int(t1);
                float sc0 = __int_as_float((i0 + EXPC) << 23);
                float sc1 = __int_as_float((i1 + EXPC) << 23);
                ull scaleP = pack2(sc0, sc1);

                acc[p] = fma2(pl, scaleP, acc[p]);
            }
        }
    }

    float* ob = out + (size_t)b * NC + base;
    #pragma unroll
    for (int p = 0; p < NPAIR; p++) {
        float a0, a1;
        unpack2(acc[p], a0, a1);
        ob[tid + (2 * p)     * BDIM] = a0;
        ob[tid + (2 * p + 1) * BDIM] = a1;
    }
}

extern "C" void kernel_launch(void* const* d_in, const int* in_sizes, int n_in,
                              void* d_out, int out_size) {
    const float* mo = (const float*)d_in[0];   // model_out: (512, 64, 6) f32
    const float* X  = (const float*)d_in[1];   // X:         (512, 2048, 2) f32
    float* out      = (float*)d_out;           // out:       (512, 2048) f32
    (void)in_sizes; (void)n_in; (void)out_size;

    mixture_kernel<<<NB * SPLIT, BDIM>>>(mo, X, out);
}